// round 11
// baseline (speedup 1.0000x reference)
#include <cuda_runtime.h>

// Swap_18957985644706: channel-group roll permutation — persistent-grid variant.
// x: (B=32, C=256, H=64, W=64) fp32, row-major.
// out group 0 (c in [0,64)):    x[b, c+64, (h-1)%64, w]
// out group 1 (c in [64,128)):  x[b, c-64, (h+1)%64, w]
// out group 2 (c in [128,192)): x[b, c+64, h, (w-1)%64]
// out group 3 (c in [192,256)): x[b, c-64, h, (w+1)%64]
//
// Established (R2-R10): the kernel is HBM-roofline-bound (~94% of spec);
// ILP/vector-width/cache-policy/occupancy levers are all neutral. This
// round tests the last structural lever: a persistent single-wave grid
// (592 CTAs = 148 SMs x 4) with a grid-stride loop, eliminating ~13 wave
// transitions (~2.4k cyc each) and repeated CTA-launch transients.
//
// Per-iteration body is the proven ILP=4 float4 shape: QUARTER = 2^21
// chunk stride lands in the batch bits, so c/h/w4/group and the shuffle
// lane pattern depend only on (i mod 2^21) and the 4 loads front-batch.
// All memory ops are aligned 128-bit, fully coalesced both directions;
// the +/-1 W-shift (groups 2/3) is one warp shuffle across the 16-lane
// row group.

static constexpr unsigned TOTAL_F4 = 32u * 256u * 64u * 16u;   // 8,388,608 = 2^23
static constexpr unsigned QUARTER  = TOTAL_F4 / 4u;            // 2,097,152 = 2^21
static constexpr unsigned THREADS  = 256u;
static constexpr unsigned NBLOCKS  = 148u * 4u;                // one full wave (592)
static constexpr unsigned STRIDE   = NBLOCKS * THREADS;        // 151,552 threads

__global__ void __launch_bounds__(THREADS) swap_roll_kernel(
    const float4* __restrict__ in, float4* __restrict__ out)
{
    unsigned lane = threadIdx.x & 31u;
    unsigned start = blockIdx.x * THREADS + threadIdx.x;

    // Precompute both shuffle source lanes (loop-invariant).
    unsigned laneM1 = (lane & 16u) | ((lane + 15u) & 15u);   // w-1 wrap
    unsigned laneP1 = (lane & 16u) | ((lane + 1u)  & 15u);   // w+1 wrap

    for (unsigned tid = start; tid < QUARTER; tid += STRIDE) {
        unsigned w4 = tid & 15u;          // float4 index within row (0..15)
        unsigned h  = (tid >> 4) & 63u;
        unsigned c  = (tid >> 10) & 255u;
        unsigned b  = tid >> 18;          // low batch bits (0..7)

        unsigned g = c >> 6;              // group 0..3 (warp-uniform)

        unsigned src_c, src_h;
        if (g == 0u)      { src_c = c + 64u; src_h = (h + 63u) & 63u; }
        else if (g == 1u) { src_c = c - 64u; src_h = (h + 1u)  & 63u; }
        else if (g == 2u) { src_c = c + 64u; src_h = h; }
        else              { src_c = c - 64u; src_h = h; }

        unsigned src = ((b * 256u + src_c) * 64u + src_h) * 16u + w4;

        // Front-batched independent loads (MLP = 4)
        float4 v0 = in[src];
        float4 v1 = in[src +      QUARTER];
        float4 v2 = in[src + 2u * QUARTER];
        float4 v3 = in[src + 3u * QUARTER];

        if (g < 2u) {
            out[tid]                = v0;
            out[tid +      QUARTER] = v1;
            out[tid + 2u * QUARTER] = v2;
            out[tid + 3u * QUARTER] = v3;
        } else if (g == 2u) {
            // out[w] = in[w-1]: {prev.w, v.x, v.y, v.z}
            float p0 = __shfl_sync(0xffffffffu, v0.w, (int)laneM1);
            float p1 = __shfl_sync(0xffffffffu, v1.w, (int)laneM1);
            float p2 = __shfl_sync(0xffffffffu, v2.w, (int)laneM1);
            float p3 = __shfl_sync(0xffffffffu, v3.w, (int)laneM1);
            out[tid]                = make_float4(p0, v0.x, v0.y, v0.z);
            out[tid +      QUARTER] = make_float4(p1, v1.x, v1.y, v1.z);
            out[tid + 2u * QUARTER] = make_float4(p2, v2.x, v2.y, v2.z);
            out[tid + 3u * QUARTER] = make_float4(p3, v3.x, v3.y, v3.z);
        } else {
            // out[w] = in[w+1]: {v.y, v.z, v.w, next.x}
            float n0 = __shfl_sync(0xffffffffu, v0.x, (int)laneP1);
            float n1 = __shfl_sync(0xffffffffu, v1.x, (int)laneP1);
            float n2 = __shfl_sync(0xffffffffu, v2.x, (int)laneP1);
            float n3 = __shfl_sync(0xffffffffu, v3.x, (int)laneP1);
            out[tid]                = make_float4(v0.y, v0.z, v0.w, n0);
            out[tid +      QUARTER] = make_float4(v1.y, v1.z, v1.w, n1);
            out[tid + 2u * QUARTER] = make_float4(v2.y, v2.z, v2.w, n2);
            out[tid + 3u * QUARTER] = make_float4(v3.y, v3.z, v3.w, n3);
        }
    }
}

extern "C" void kernel_launch(void* const* d_in, const int* in_sizes, int n_in,
                              void* d_out, int out_size)
{
    const float4* in  = (const float4*)d_in[0];
    float4*       out = (float4*)d_out;
    swap_roll_kernel<<<NBLOCKS, THREADS>>>(in, out);
}

// round 12
// speedup vs baseline: 1.0870x; 1.0870x over previous
#include <cuda_runtime.h>

// Swap_18957985644706: channel-group roll permutation — FINAL kernel.
// x: (B=32, C=256, H=64, W=64) fp32, row-major.
// out group 0 (c in [0,64)):    x[b, c+64, (h-1)%64, w]
// out group 1 (c in [64,128)):  x[b, c-64, (h+1)%64, w]
// out group 2 (c in [128,192)): x[b, c+64, h, (w-1)%64]
// out group 3 (c in [192,256)): x[b, c-64, h, (w+1)%64]
//
// CONVERGED (R2-R11 evidence): ILP {1,4,8} x vector {128b,256b} x block
// {256,512} x {default,streaming} x {free,occ-capped} all tie at
// 43.49-43.97us; persistent single-wave grid REGRESSED to 47.6us (loop-
// carried issue dependence cut chip-wide outstanding loads — oversubscribed
// grids hide wave transitions via work-stealing for free on memory-bound
// kernels). Best ncu captures: ~7.6 TB/s combined read+write ≈ 94% of
// 8 TB/s HBM3e spec. Zero reuse, zero compute — every byte crosses HBM
// once each direction; this is the roofline floor.
//
// Shape: ILP=4, 256-thread blocks, 8192 CTAs, plain LDG.128/STG.128,
// natural regalloc. All memory ops aligned 128-bit, fully 256B-row
// coalesced on both load and store sides. Height-roll groups (0/1) are
// pure row remaps; the +/-1 width-shift (groups 2/3) is one warp shuffle
// across the 16-lane row group (64 floats/row = 16 float4 lanes) instead
// of misaligned loads. QUARTER = 2^21 lands entirely in the batch bits of
// the linear index, so c/h/w4/group and the shuffle lane pattern are
// shared across the 4 chunks per thread and the 4 loads front-batch
// (MLP = 4).

static constexpr unsigned TOTAL_F4 = 32u * 256u * 64u * 16u;   // 8,388,608 = 2^23
static constexpr unsigned QUARTER  = TOTAL_F4 / 4u;            // 2,097,152 = 2^21
static constexpr unsigned THREADS  = 256u;

__global__ void __launch_bounds__(THREADS) swap_roll_kernel(
    const float4* __restrict__ in, float4* __restrict__ out)
{
    unsigned tid = blockIdx.x * THREADS + threadIdx.x;

    unsigned w4 = tid & 15u;          // float4 index within row (0..15)
    unsigned h  = (tid >> 4) & 63u;
    unsigned c  = (tid >> 10) & 255u;
    unsigned b  = tid >> 18;          // low batch bits (0..7)

    unsigned g = c >> 6;              // group 0..3 (warp-uniform)
    unsigned lane = threadIdx.x & 31u;

    unsigned src_c, src_h;
    if (g == 0u)      { src_c = c + 64u; src_h = (h + 63u) & 63u; }
    else if (g == 1u) { src_c = c - 64u; src_h = (h + 1u)  & 63u; }
    else if (g == 2u) { src_c = c + 64u; src_h = h; }
    else              { src_c = c - 64u; src_h = h; }

    unsigned src = ((b * 256u + src_c) * 64u + src_h) * 16u + w4;

    // Front-batched independent loads (MLP = 4)
    float4 v0 = in[src];
    float4 v1 = in[src +      QUARTER];
    float4 v2 = in[src + 2u * QUARTER];
    float4 v3 = in[src + 3u * QUARTER];

    if (g < 2u) {
        out[tid]                = v0;
        out[tid +      QUARTER] = v1;
        out[tid + 2u * QUARTER] = v2;
        out[tid + 3u * QUARTER] = v3;
    } else if (g == 2u) {
        // out[w] = in[w-1]: {prev.w, v.x, v.y, v.z}; prev = lane-1 within
        // the 16-lane row group (wrap inside the half-warp row).
        unsigned srcLane = (lane & 16u) | ((lane + 15u) & 15u);
        float p0 = __shfl_sync(0xffffffffu, v0.w, (int)srcLane);
        float p1 = __shfl_sync(0xffffffffu, v1.w, (int)srcLane);
        float p2 = __shfl_sync(0xffffffffu, v2.w, (int)srcLane);
        float p3 = __shfl_sync(0xffffffffu, v3.w, (int)srcLane);
        out[tid]                = make_float4(p0, v0.x, v0.y, v0.z);
        out[tid +      QUARTER] = make_float4(p1, v1.x, v1.y, v1.z);
        out[tid + 2u * QUARTER] = make_float4(p2, v2.x, v2.y, v2.z);
        out[tid + 3u * QUARTER] = make_float4(p3, v3.x, v3.y, v3.z);
    } else {
        // out[w] = in[w+1]: {v.y, v.z, v.w, next.x}; next = lane+1 within
        // the 16-lane row group (wrap).
        unsigned srcLane = (lane & 16u) | ((lane + 1u) & 15u);
        float n0 = __shfl_sync(0xffffffffu, v0.x, (int)srcLane);
        float n1 = __shfl_sync(0xffffffffu, v1.x, (int)srcLane);
        float n2 = __shfl_sync(0xffffffffu, v2.x, (int)srcLane);
        float n3 = __shfl_sync(0xffffffffu, v3.x, (int)srcLane);
        out[tid]                = make_float4(v0.y, v0.z, v0.w, n0);
        out[tid +      QUARTER] = make_float4(v1.y, v1.z, v1.w, n1);
        out[tid + 2u * QUARTER] = make_float4(v2.y, v2.z, v2.w, n2);
        out[tid + 3u * QUARTER] = make_float4(v3.y, v3.z, v3.w, n3);
    }
}

extern "C" void kernel_launch(void* const* d_in, const int* in_sizes, int n_in,
                              void* d_out, int out_size)
{
    const float4* in  = (const float4*)d_in[0];
    float4*       out = (float4*)d_out;
    swap_roll_kernel<<<QUARTER / THREADS, THREADS>>>(in, out);
}